// round 4
// baseline (speedup 1.0000x reference)
#include <cuda_runtime.h>
#include <cuda_bf16.h>

#define DMODEL 4096
#define NEXP   64
#define TPB    64               // tokens per block
#define KC     32               // K-chunk per stage
#define THREADS 128
#define NIT    (DMODEL / KC)    // 128 K-iterations

// Fused router: logits GEMM (x@W+b) + softmax(64) + top-2 + renorm.
// 128 threads: tx = tid&7 -> 8 experts each; ty = tid>>3 -> 4 tokens each.
// Double-buffered smem, register-prefetch pipeline, xs stored k-major so the
// inner loop is 3x LDS.128 + 32 FFMA.
__global__ __launch_bounds__(THREADS, 2) void router_kernel(
    const float* __restrict__ x, const float* __restrict__ W,
    const float* __restrict__ b,
    float* __restrict__ probs_out, float* __restrict__ tkp_out,
    float* __restrict__ tki_out)
{
    __shared__ float xs[2][KC][TPB];    // [stage][k][token]  16 KB
    __shared__ float ws[2][KC][NEXP];   // [stage][k][expert] 16 KB

    const int tid  = threadIdx.x;
    const int tx   = tid & 7;           // expert group (8 experts)
    const int ty   = tid >> 3;          // token group  (4 tokens), 0..15
    const int tok0 = blockIdx.x * TPB;

    // ---- per-thread load assignments (4 float4 each for x and W) ----
    // x tile: 64 tok x 32 k = 512 float4 ; W tile: 32 k x 64 exp = 512 float4
    int xt[4], xc[4], wk[4], wc[4];
    #pragma unroll
    for (int r = 0; r < 4; r++) {
        int f4 = tid + r * THREADS;     // 0..511
        xt[r] = f4 >> 3;                // token 0..63
        xc[r] = (f4 & 7) * 4;           // k offset 0..28
        wk[r] = f4 >> 4;                // k row 0..31
        wc[r] = (f4 & 15) * 4;          // expert col 0..60
    }

    float acc[4][8];
    #pragma unroll
    for (int i = 0; i < 4; i++)
        #pragma unroll
        for (int j = 0; j < 8; j++) acc[i][j] = 0.f;

    float4 xr[4], wr[4];

    // ---- prologue: fetch tile 0 and stage it ----
    #pragma unroll
    for (int r = 0; r < 4; r++) {
        xr[r] = *reinterpret_cast<const float4*>(
            &x[(size_t)(tok0 + xt[r]) * DMODEL + xc[r]]);
        wr[r] = *reinterpret_cast<const float4*>(&W[(size_t)wk[r] * NEXP + wc[r]]);
    }
    #pragma unroll
    for (int r = 0; r < 4; r++) {
        xs[0][xc[r] + 0][xt[r]] = xr[r].x;
        xs[0][xc[r] + 1][xt[r]] = xr[r].y;
        xs[0][xc[r] + 2][xt[r]] = xr[r].z;
        xs[0][xc[r] + 3][xt[r]] = xr[r].w;
        *reinterpret_cast<float4*>(&ws[0][wk[r]][wc[r]]) = wr[r];
    }

    #pragma unroll 1
    for (int it = 0; it < NIT; it++) {
        const int s = it & 1;
        __syncthreads();   // stage s fully written & visible; stage s^1 free

        // prefetch next tile into registers (latency hidden by compute below)
        if (it + 1 < NIT) {
            const int k0 = (it + 1) * KC;
            #pragma unroll
            for (int r = 0; r < 4; r++) {
                xr[r] = *reinterpret_cast<const float4*>(
                    &x[(size_t)(tok0 + xt[r]) * DMODEL + k0 + xc[r]]);
                wr[r] = *reinterpret_cast<const float4*>(
                    &W[(size_t)(k0 + wk[r]) * NEXP + wc[r]]);
            }
        }

        // ---- compute: 32 k-steps, 32 FMA per step per thread ----
        #pragma unroll
        for (int kk = 0; kk < KC; kk++) {
            float4 xa = *reinterpret_cast<const float4*>(&xs[s][kk][ty * 4]);
            float4 wa = *reinterpret_cast<const float4*>(&ws[s][kk][tx * 8]);
            float4 wb = *reinterpret_cast<const float4*>(&ws[s][kk][tx * 8 + 4]);
            const float xv[4] = {xa.x, xa.y, xa.z, xa.w};
            const float wv[8] = {wa.x, wa.y, wa.z, wa.w, wb.x, wb.y, wb.z, wb.w};
            #pragma unroll
            for (int i = 0; i < 4; i++)
                #pragma unroll
                for (int j = 0; j < 8; j++)
                    acc[i][j] = fmaf(xv[i], wv[j], acc[i][j]);
        }

        // stage next tile into the other buffer
        if (it + 1 < NIT) {
            const int d = s ^ 1;
            #pragma unroll
            for (int r = 0; r < 4; r++) {
                xs[d][xc[r] + 0][xt[r]] = xr[r].x;
                xs[d][xc[r] + 1][xt[r]] = xr[r].y;
                xs[d][xc[r] + 2][xt[r]] = xr[r].z;
                xs[d][xc[r] + 3][xt[r]] = xr[r].w;
                *reinterpret_cast<float4*>(&ws[d][wk[r]][wc[r]]) = wr[r];
            }
        }
    }

    // ---- epilogue: bias + softmax + top-2 over 8-lane segments ----
    float4 ba = *reinterpret_cast<const float4*>(&b[tx * 8]);
    float4 bb = *reinterpret_cast<const float4*>(&b[tx * 8 + 4]);
    const float bias[8] = {ba.x, ba.y, ba.z, ba.w, bb.x, bb.y, bb.z, bb.w};
    const unsigned mask = 0xffffffffu;

    #pragma unroll
    for (int i = 0; i < 4; i++) {
        const int token = tok0 + ty * 4 + i;
        float v[8];
        #pragma unroll
        for (int j = 0; j < 8; j++) v[j] = acc[i][j] + bias[j];

        float m = v[0];
        #pragma unroll
        for (int j = 1; j < 8; j++) m = fmaxf(m, v[j]);
        #pragma unroll
        for (int sft = 4; sft >= 1; sft >>= 1)
            m = fmaxf(m, __shfl_xor_sync(mask, m, sft, 8));

        float e[8], sum = 0.f;
        #pragma unroll
        for (int j = 0; j < 8; j++) { e[j] = __expf(v[j] - m); sum += e[j]; }
        #pragma unroll
        for (int sft = 4; sft >= 1; sft >>= 1)
            sum += __shfl_xor_sync(mask, sum, sft, 8);

        const float inv = 1.f / sum;
        float p[8];
        #pragma unroll
        for (int j = 0; j < 8; j++) p[j] = e[j] * inv;

        *reinterpret_cast<float4*>(&probs_out[(size_t)token * NEXP + tx * 8]) =
            make_float4(p[0], p[1], p[2], p[3]);
        *reinterpret_cast<float4*>(&probs_out[(size_t)token * NEXP + tx * 8 + 4]) =
            make_float4(p[4], p[5], p[6], p[7]);

        // local top-2 of 8
        float p1 = -1.f, p2 = -1.f;
        int e1 = 0, e2 = 0;
        #pragma unroll
        for (int j = 0; j < 8; j++) {
            float pv = p[j];
            int   ei = tx * 8 + j;
            if (pv > p1)      { p2 = p1; e2 = e1; p1 = pv; e1 = ei; }
            else if (pv > p2) { p2 = pv; e2 = ei; }
        }
        // merge across 8 lanes
        #pragma unroll
        for (int sft = 1; sft < 8; sft <<= 1) {
            float op1 = __shfl_xor_sync(mask, p1, sft, 8);
            int   oe1 = __shfl_xor_sync(mask, e1, sft, 8);
            float op2 = __shfl_xor_sync(mask, p2, sft, 8);
            int   oe2 = __shfl_xor_sync(mask, e2, sft, 8);
            if (op1 > p1) {
                if (p1 > op2) { p2 = p1;  e2 = e1;  }
                else          { p2 = op2; e2 = oe2; }
                p1 = op1; e1 = oe1;
            } else if (op1 > p2) {
                p2 = op1; e2 = oe1;
            }
        }

        if (tx == 0) {
            float is2 = 1.f / (p1 + p2 + 1e-9f);
            tkp_out[(size_t)token * 2]     = p1 * is2;
            tkp_out[(size_t)token * 2 + 1] = p2 * is2;
            tki_out[(size_t)token * 2]     = (float)e1;
            tki_out[(size_t)token * 2 + 1] = (float)e2;
        }
    }
}

extern "C" void kernel_launch(void* const* d_in, const int* in_sizes, int n_in,
                              void* d_out, int out_size) {
    const float* x = (const float*)d_in[0];   // [4,4096,4096]
    const float* W = (const float*)d_in[1];   // [4096,64]
    const float* b = (const float*)d_in[2];   // [64]

    const int n_tokens = in_sizes[0] / DMODEL;        // 16384
    float* probs = (float*)d_out;                     // n_tokens*64
    float* tkp   = probs + (size_t)n_tokens * NEXP;   // n_tokens*2
    float* tki   = tkp + (size_t)n_tokens * 2;        // n_tokens*2

    dim3 grid(n_tokens / TPB);                        // 256 blocks
    router_kernel<<<grid, THREADS>>>(x, W, b, probs, tkp, tki);
}